// round 16
// baseline (speedup 1.0000x reference)
#include <cuda_runtime.h>
#include <cuda_bf16.h>

// Model dims
#define KTOK 64
#define DIN  49
#define DM   16
#define FFD  32

// Plain KV layout: row j of a batch at j*32 floats (K[16] | V[16]).
// Reads are warp-uniform broadcasts -> conflict-free without any swizzle.
// Writes (once, stage 2a) hit stride-128B conflicts; negligible one-time cost.
#define KV_BATCHF 2048                   // floats per batch
#define KV_TOTALF (4 * KV_BATCHF)        // 8192 floats = 32768 B dynamic smem
#define KV_ROW(j) ((j) * 32)
#define XCHUNK    1568                   // 32 rows * 49 floats per batch chunk

typedef unsigned long long u64;

__device__ __forceinline__ u64 splat2(float v) {
    u64 r; unsigned u = __float_as_uint(v);
    asm("mov.b64 %0, {%1, %1};" : "=l"(r) : "r"(u));
    return r;
}
__device__ __forceinline__ void ffma2(u64& d, u64 a, u64 b) {
    asm("fma.rn.f32x2 %0, %1, %2, %3;" : "=l"(d) : "l"(a), "l"(b), "l"(d));
}
__device__ __forceinline__ u64 mul2(u64 a, u64 b) {
    u64 r; asm("mul.rn.f32x2 %0, %1, %2;" : "=l"(r) : "l"(a), "l"(b)); return r;
}
__device__ __forceinline__ u64 add2(u64 a, u64 b) {
    u64 r; asm("add.rn.f32x2 %0, %1, %2;" : "=l"(r) : "l"(a), "l"(b)); return r;
}
__device__ __forceinline__ float2 unpack2(u64 p) {
    unsigned lo, hi;
    asm("mov.b64 {%0, %1}, %2;" : "=r"(lo), "=r"(hi) : "l"(p));
    return make_float2(__uint_as_float(lo), __uint_as_float(hi));
}

struct __align__(16) SW {            // 3044 floats = 12176 B (posw in global/L2)
    float pwt[DIN * DM];     // [i][d]
    float wqkvt[DM * 48];    // [d][e]
    float wot[DM * DM];      // [d][o]
    float w1t[DM * FFD];     // [d][f]
    float w2t[FFD * DM];     // [f][o]
    float pb[DM];
    float bqkv[48];
    float ob[DM];
    float ln1g[DM], ln1b[DM];
    float b1[FFD];
    float b2[DM];
    float ln2g[DM], ln2b[DM];
    float hw[DM];
    float hb;
    float pad[3];
};

__global__ void __launch_bounds__(128, 5)
tx_kernel(const float* __restrict__ x,
          const float* __restrict__ proj_w, const float* __restrict__ proj_b,
          const float* __restrict__ pos,
          const float* __restrict__ in_proj_w, const float* __restrict__ in_proj_b,
          const float* __restrict__ out_w, const float* __restrict__ out_b,
          const float* __restrict__ ln1_g, const float* __restrict__ ln1_b,
          const float* __restrict__ lin1_w, const float* __restrict__ lin1_b,
          const float* __restrict__ lin2_w, const float* __restrict__ lin2_b,
          const float* __restrict__ ln2_g, const float* __restrict__ ln2_b,
          const float* __restrict__ head_w, const float* __restrict__ head_b,
          float* __restrict__ out)
{
    __shared__ SW sw;
    extern __shared__ __align__(16) float kvbuf[];   // x staging, then K/V

    const int tid = threadIdx.x;

    for (int idx = tid; idx < DIN * DM; idx += 128) {
        int i = idx >> 4, d = idx & 15;
        sw.pwt[idx] = proj_w[d * DIN + i];
    }
    for (int idx = tid; idx < DM * 48; idx += 128) {
        int d = idx / 48, e = idx % 48;
        sw.wqkvt[idx] = in_proj_w[e * DM + d];
    }
    for (int idx = tid; idx < DM * DM; idx += 128) {
        int d = idx >> 4, o = idx & 15;
        sw.wot[idx] = out_w[o * DM + d];
    }
    for (int idx = tid; idx < DM * FFD; idx += 128) {
        int d = idx >> 5, f = idx & 31;
        sw.w1t[idx] = lin1_w[f * DM + d];
    }
    for (int idx = tid; idx < FFD * DM; idx += 128) {
        int f = idx >> 4, o = idx & 15;
        sw.w2t[idx] = lin2_w[o * FFD + f];
    }
    if (tid < DM) {
        sw.pb[tid]   = proj_b[tid];
        sw.ob[tid]   = out_b[tid];
        sw.ln1g[tid] = ln1_g[tid];
        sw.ln1b[tid] = ln1_b[tid];
        sw.b2[tid]   = lin2_b[tid];
        sw.ln2g[tid] = ln2_g[tid];
        sw.ln2b[tid] = ln2_b[tid];
        sw.hw[tid]   = head_w[tid];
    }
    if (tid < 48) sw.bqkv[tid] = in_proj_b[tid];
    if (tid < FFD) sw.b1[tid]  = lin1_b[tid];
    if (tid == 0)  sw.hb = head_b[0];

    const int b0   = blockIdx.x * 4;
    const int g    = tid >> 5;        // warp <-> batch
    const int lane = tid & 31;        // tokens: lane, lane+32

    // prefetch pos rows for both tokens from global (4KB table, L2-resident)
    u64 pos0[8], pos1[8];
    {
        const ulonglong2* pg0 = reinterpret_cast<const ulonglong2*>(pos + lane * DM);
        const ulonglong2* pg1 = reinterpret_cast<const ulonglong2*>(pos + (lane + 32) * DM);
#pragma unroll
        for (int p = 0; p < 4; p++) {
            ulonglong2 t0 = pg0[p], t1 = pg1[p];
            pos0[2*p] = t0.x; pos0[2*p+1] = t0.y;
            pos1[2*p] = t1.x; pos1[2*p+1] = t1.y;
        }
    }

    float h0[DM], h1[DM];

    // ---- stage 1: proj + bias + pos, chunked x staging ----
    const float4* xg = reinterpret_cast<const float4*>(x);
#pragma unroll
    for (int c = 0; c < 2; c++) {
        __syncthreads();
        float4* dst = reinterpret_cast<float4*>(kvbuf);
        for (int idx = tid; idx < 1568; idx += 128) {
            int gg  = idx / 392;
            int off = idx - gg * 392;
            dst[idx] = xg[(size_t)(b0 + gg) * 784 + c * 392 + off];
        }
        __syncthreads();

        u64 h2[8];
        const ulonglong2* pb2 = reinterpret_cast<const ulonglong2*>(sw.pb);
        const u64* pw = c ? pos1 : pos0;
#pragma unroll
        for (int p = 0; p < 4; p++) {
            ulonglong2 bq = pb2[p];
            h2[2*p]   = add2(bq.x, pw[2*p]);
            h2[2*p+1] = add2(bq.y, pw[2*p+1]);
        }
        const float* xrow = kvbuf + g * XCHUNK + lane * DIN;
#pragma unroll 7
        for (int i = 0; i < DIN; i++) {
            u64 xv = splat2(xrow[i]);
            const ulonglong2* wr = reinterpret_cast<const ulonglong2*>(&sw.pwt[i * DM]);
            ulonglong2 w0 = wr[0], w1 = wr[1], w2 = wr[2], w3 = wr[3];
            ffma2(h2[0], xv, w0.x); ffma2(h2[1], xv, w0.y);
            ffma2(h2[2], xv, w1.x); ffma2(h2[3], xv, w1.y);
            ffma2(h2[4], xv, w2.x); ffma2(h2[5], xv, w2.y);
            ffma2(h2[6], xv, w3.x); ffma2(h2[7], xv, w3.y);
        }
        float* hh = c ? h1 : h0;
#pragma unroll
        for (int p = 0; p < 8; p++) {
            float2 t = unpack2(h2[p]); hh[2*p] = t.x; hh[2*p+1] = t.y;
        }
    }
    __syncthreads();   // x reads done; kvbuf becomes K/V

    // ---- stage 2a: K,V projection for both tokens, write to smem ----
    {
        u64 kv0[16], kv1[16];
        const ulonglong2* bq = reinterpret_cast<const ulonglong2*>(sw.bqkv + 16);
#pragma unroll
        for (int p = 0; p < 8; p++) {
            ulonglong2 t = bq[p];
            kv0[2*p] = t.x; kv0[2*p+1] = t.y;
            kv1[2*p] = t.x; kv1[2*p+1] = t.y;
        }
#pragma unroll
        for (int d = 0; d < DM; d++) {
            u64 hv0 = splat2(h0[d]), hv1 = splat2(h1[d]);
            const ulonglong2* wr = reinterpret_cast<const ulonglong2*>(&sw.wqkvt[d * 48 + 16]);
#pragma unroll
            for (int p = 0; p < 8; p++) {
                ulonglong2 w = wr[p];
                ffma2(kv0[2*p],   hv0, w.x); ffma2(kv0[2*p+1], hv0, w.y);
                ffma2(kv1[2*p],   hv1, w.x); ffma2(kv1[2*p+1], hv1, w.y);
            }
        }
        ulonglong2* r0 = reinterpret_cast<ulonglong2*>(kvbuf + g * KV_BATCHF + KV_ROW(lane));
        // KV_ROW(lane+32) = KV_ROW(lane) + 1024 floats = +256 ulonglong2
        ulonglong2* r1 = r0 + 256;
#pragma unroll
        for (int p = 0; p < 8; p++) {
            r0[p] = make_ulonglong2(kv0[2*p], kv0[2*p+1]);
            r1[p] = make_ulonglong2(kv1[2*p], kv1[2*p+1]);
        }
    }

    // ---- stage 2b: Q projection (pre-scaled by 1/sqrt(8)) ----
    u64 q0[8], q1[8];
    {
        const ulonglong2* bq = reinterpret_cast<const ulonglong2*>(sw.bqkv);
#pragma unroll
        for (int p = 0; p < 4; p++) {
            ulonglong2 t = bq[p];
            q0[2*p] = t.x; q0[2*p+1] = t.y;
            q1[2*p] = t.x; q1[2*p+1] = t.y;
        }
#pragma unroll
        for (int d = 0; d < DM; d++) {
            u64 hv0 = splat2(h0[d]), hv1 = splat2(h1[d]);
            const ulonglong2* wr = reinterpret_cast<const ulonglong2*>(&sw.wqkvt[d * 48]);
#pragma unroll
            for (int p = 0; p < 4; p++) {
                ulonglong2 w = wr[p];
                ffma2(q0[2*p],   hv0, w.x); ffma2(q0[2*p+1], hv0, w.y);
                ffma2(q1[2*p],   hv1, w.x); ffma2(q1[2*p+1], hv1, w.y);
            }
        }
        u64 sc2 = splat2(0.35355339059327373f);
#pragma unroll
        for (int p = 0; p < 8; p++) { q0[p] = mul2(q0[p], sc2); q1[p] = mul2(q1[p], sc2); }
    }
    __syncwarp();   // KV rows are warp-private (warp <-> batch)

    // ---- stage 3: attention, single pass, no max subtraction ----
    // |scores| << 1 by input construction; exp() safe, math identical to
    // max-subtracted softmax.
    float ctx0[DM], ctx1[DM];
    {
        const float* kvb = kvbuf + g * KV_BATCHF;
        float s00 = 0.f, s01 = 0.f, s10 = 0.f, s11 = 0.f;
        u64 ca0[8], ca1[8];
#pragma unroll
        for (int p = 0; p < 8; p++) { ca0[p] = 0ull; ca1[p] = 0ull; }
#pragma unroll 4
        for (int j = 0; j < KTOK; j++) {
            const ulonglong2* kr = reinterpret_cast<const ulonglong2*>(kvb + KV_ROW(j));
            ulonglong2 k0 = kr[0], k1 = kr[1], k2 = kr[2], k3 = kr[3];
            u64 a00 = mul2(q0[0], k0.x);
            ffma2(a00, q0[1], k0.y); ffma2(a00, q0[2], k1.x); ffma2(a00, q0[3], k1.y);
            u64 a01 = mul2(q0[4], k2.x);
            ffma2(a01, q0[5], k2.y); ffma2(a01, q0[6], k3.x); ffma2(a01, q0[7], k3.y);
            u64 a10 = mul2(q1[0], k0.x);
            ffma2(a10, q1[1], k0.y); ffma2(a10, q1[2], k1.x); ffma2(a10, q1[3], k1.y);
            u64 a11 = mul2(q1[4], k2.x);
            ffma2(a11, q1[5], k2.y); ffma2(a11, q1[6], k3.x); ffma2(a11, q1[7], k3.y);

            float2 t00 = unpack2(a00), t01 = unpack2(a01);
            float2 t10 = unpack2(a10), t11 = unpack2(a11);
            float e00 = __expf(t00.x + t00.y);
            float e01 = __expf(t01.x + t01.y);
            float e10 = __expf(t10.x + t10.y);
            float e11 = __expf(t11.x + t11.y);
            s00 += e00; s01 += e01; s10 += e10; s11 += e11;

            ulonglong2 v0 = kr[4], v1 = kr[5], v2 = kr[6], v3 = kr[7];
            u64 p00 = splat2(e00), p01 = splat2(e01);
            u64 p10 = splat2(e10), p11 = splat2(e11);
            ffma2(ca0[0], p00, v0.x); ffma2(ca0[1], p00, v0.y);
            ffma2(ca0[2], p00, v1.x); ffma2(ca0[3], p00, v1.y);
            ffma2(ca0[4], p01, v2.x); ffma2(ca0[5], p01, v2.y);
            ffma2(ca0[6], p01, v3.x); ffma2(ca0[7], p01, v3.y);
            ffma2(ca1[0], p10, v0.x); ffma2(ca1[1], p10, v0.y);
            ffma2(ca1[2], p10, v1.x); ffma2(ca1[3], p10, v1.y);
            ffma2(ca1[4], p11, v2.x); ffma2(ca1[5], p11, v2.y);
            ffma2(ca1[6], p11, v3.x); ffma2(ca1[7], p11, v3.y);
        }
        float i00 = __fdividef(1.0f, s00), i01 = __fdividef(1.0f, s01);
        float i10 = __fdividef(1.0f, s10), i11 = __fdividef(1.0f, s11);
#pragma unroll
        for (int p = 0; p < 8; p++) {
            float2 t0 = unpack2(ca0[p]), t1 = unpack2(ca1[p]);
            float f0 = (p < 4) ? i00 : i01;
            float f1 = (p < 4) ? i10 : i11;
            ctx0[2*p] = t0.x * f0; ctx0[2*p+1] = t0.y * f0;
            ctx1[2*p] = t1.x * f1; ctx1[2*p+1] = t1.y * f1;
        }
    }

    // ---- stage 4: out proj + residual + LN1 ----
    {
        u64 ao0[8], ao1[8];
        const ulonglong2* ob2 = reinterpret_cast<const ulonglong2*>(sw.ob);
#pragma unroll
        for (int p = 0; p < 4; p++) {
            ulonglong2 t = ob2[p];
            ao0[2*p] = t.x; ao0[2*p+1] = t.y;
            ao1[2*p] = t.x; ao1[2*p+1] = t.y;
        }
#pragma unroll
        for (int d = 0; d < DM; d++) {
            u64 c0 = splat2(ctx0[d]), c1 = splat2(ctx1[d]);
            const ulonglong2* wr = reinterpret_cast<const ulonglong2*>(&sw.wot[d * DM]);
#pragma unroll
            for (int p = 0; p < 4; p++) {
                ulonglong2 w = wr[p];
                ffma2(ao0[2*p],   c0, w.x); ffma2(ao0[2*p+1], c0, w.y);
                ffma2(ao1[2*p],   c1, w.x); ffma2(ao1[2*p+1], c1, w.y);
            }
        }
#pragma unroll
        for (int p = 0; p < 8; p++) {
            float2 t0 = unpack2(ao0[p]), t1 = unpack2(ao1[p]);
            h0[2*p] += t0.x; h0[2*p+1] += t0.y;
            h1[2*p] += t1.x; h1[2*p+1] += t1.y;
        }
#pragma unroll
        for (int t = 0; t < 2; t++) {
            float* hh = t ? h1 : h0;
            float mu = 0.f;
#pragma unroll
            for (int d = 0; d < DM; d++) mu += hh[d];
            mu *= (1.0f / 16.0f);
            float var = 0.f;
#pragma unroll
            for (int d = 0; d < DM; d++) { float z = hh[d] - mu; var = fmaf(z, z, var); }
            var *= (1.0f / 16.0f);
            float rstd = rsqrtf(var + 1e-5f);
#pragma unroll
            for (int d = 0; d < DM; d++)
                hh[d] = (hh[d] - mu) * rstd * sw.ln1g[d] + sw.ln1b[d];
        }
    }

    // ---- stage 5: FFN + residual + LN2 ----
    {
        u64 ff0[16], ff1[16];
        const ulonglong2* b12 = reinterpret_cast<const ulonglong2*>(sw.b1);
#pragma unroll
        for (int p = 0; p < 8; p++) {
            ulonglong2 t = b12[p];
            ff0[2*p] = t.x; ff0[2*p+1] = t.y;
            ff1[2*p] = t.x; ff1[2*p+1] = t.y;
        }
#pragma unroll
        for (int d = 0; d < DM; d++) {
            u64 hv0 = splat2(h0[d]), hv1 = splat2(h1[d]);
            const ulonglong2* wr = reinterpret_cast<const ulonglong2*>(&sw.w1t[d * FFD]);
#pragma unroll
            for (int p = 0; p < 8; p++) {
                ulonglong2 w = wr[p];
                ffma2(ff0[2*p],   hv0, w.x); ffma2(ff0[2*p+1], hv0, w.y);
                ffma2(ff1[2*p],   hv1, w.x); ffma2(ff1[2*p+1], hv1, w.y);
            }
        }
        u64 f20[8], f21[8];
        const ulonglong2* b22 = reinterpret_cast<const ulonglong2*>(sw.b2);
#pragma unroll
        for (int p = 0; p < 4; p++) {
            ulonglong2 t = b22[p];
            f20[2*p] = t.x; f20[2*p+1] = t.y;
            f21[2*p] = t.x; f21[2*p+1] = t.y;
        }
#pragma unroll
        for (int p = 0; p < 16; p++) {           // f = 2p (x), 2p+1 (y)
            float2 u0 = unpack2(ff0[p]), u1 = unpack2(ff1[p]);
            float fa0 = fmaxf(u0.x, 0.f), fb0 = fmaxf(u0.y, 0.f);
            float fa1 = fmaxf(u1.x, 0.f), fb1 = fmaxf(u1.y, 0.f);
            u64 sa0 = splat2(fa0), sb0 = splat2(fb0);
            u64 sa1 = splat2(fa1), sb1 = splat2(fb1);
            const ulonglong2* wa = reinterpret_cast<const ulonglong2*>(&sw.w2t[(2*p) * DM]);
            const ulonglong2* wb = reinterpret_cast<const ulonglong2*>(&sw.w2t[(2*p+1) * DM]);
            ulonglong2 wa0 = wa[0], wa1 = wa[1], wa2 = wa[2], wa3 = wa[3];
            ffma2(f20[0], sa0, wa0.x); ffma2(f20[1], sa0, wa0.y);
            ffma2(f20[2], sa0, wa1.x); ffma2(f20[3], sa0, wa1.y);
            ffma2(f20[4], sa0, wa2.x); ffma2(f20[5], sa0, wa2.y);
            ffma2(f20[6], sa0, wa3.x); ffma2(f20[7], sa0, wa3.y);
            ffma2(f21[0], sa1, wa0.x); ffma2(f21[1], sa1, wa0.y);
            ffma2(f21[2], sa1, wa1.x); ffma2(f21[3], sa1, wa1.y);
            ffma2(f21[4], sa1, wa2.x); ffma2(f21[5], sa1, wa2.y);
            ffma2(f21[6], sa1, wa3.x); ffma2(f21[7], sa1, wa3.y);
            ulonglong2 wb0 = wb[0], wb1 = wb[1], wb2 = wb[2], wb3 = wb[3];
            ffma2(f20[0], sb0, wb0.x); ffma2(f20[1], sb0, wb0.y);
            ffma2(f20[2], sb0, wb1.x); ffma2(f20[3], sb0, wb1.y);
            ffma2(f20[4], sb0, wb2.x); ffma2(f20[5], sb0, wb2.y);
            ffma2(f20[6], sb0, wb3.x); ffma2(f20[7], sb0, wb3.y);
            ffma2(f21[0], sb1, wb0.x); ffma2(f21[1], sb1, wb0.y);
            ffma2(f21[2], sb1, wb1.x); ffma2(f21[3], sb1, wb1.y);
            ffma2(f21[4], sb1, wb2.x); ffma2(f21[5], sb1, wb2.y);
            ffma2(f21[6], sb1, wb3.x); ffma2(f21[7], sb1, wb3.y);
        }
#pragma unroll
        for (int p = 0; p < 8; p++) {
            float2 t0 = unpack2(f20[p]), t1 = unpack2(f21[p]);
            h0[2*p] += t0.x; h0[2*p+1] += t0.y;
            h1[2*p] += t1.x; h1[2*p+1] += t1.y;
        }
#pragma unroll
        for (int t = 0; t < 2; t++) {
            float* hh = t ? h1 : h0;
            float mu = 0.f;
#pragma unroll
            for (int d = 0; d < DM; d++) mu += hh[d];
            mu *= (1.0f / 16.0f);
            float var = 0.f;
#pragma unroll
            for (int d = 0; d < DM; d++) { float z = hh[d] - mu; var = fmaf(z, z, var); }
            var *= (1.0f / 16.0f);
            float rstd = rsqrtf(var + 1e-5f);
#pragma unroll
            for (int d = 0; d < DM; d++)
                hh[d] = (hh[d] - mu) * rstd * sw.ln2g[d] + sw.ln2b[d];
        }
    }

    // ---- stage 6: head dot + mean pool (warp == batch) ----
    float sc = 0.f;
#pragma unroll
    for (int d = 0; d < DM; d++) sc = fmaf(h0[d], sw.hw[d], sc);
#pragma unroll
    for (int d = 0; d < DM; d++) sc = fmaf(h1[d], sw.hw[d], sc);
#pragma unroll
    for (int off = 16; off >= 1; off >>= 1)
        sc += __shfl_xor_sync(0xffffffffu, sc, off);
    if (lane == 0)
        out[b0 + g] = sc * (1.0f / 64.0f) + sw.hb;
}

extern "C" void kernel_launch(void* const* d_in, const int* in_sizes, int n_in,
                              void* d_out, int out_size)
{
    const float* x         = (const float*)d_in[0];
    const float* proj_w    = (const float*)d_in[1];
    const float* proj_b    = (const float*)d_in[2];
    const float* pos       = (const float*)d_in[3];
    const float* in_proj_w = (const float*)d_in[4];
    const float* in_proj_b = (const float*)d_in[5];
    const float* out_w     = (const float*)d_in[6];
    const float* out_b     = (const float*)d_in[7];
    const float* ln1_g     = (const float*)d_in[8];
    const float* ln1_b     = (const float*)d_in[9];
    const float* lin1_w    = (const float*)d_in[10];
    const float* lin1_b    = (const float*)d_in[11];
    const float* lin2_w    = (const float*)d_in[12];
    const float* lin2_b    = (const float*)d_in[13];
    const float* ln2_g     = (const float*)d_in[14];
    const float* ln2_b     = (const float*)d_in[15];
    const float* head_w    = (const float*)d_in[16];
    const float* head_b    = (const float*)d_in[17];
    float* out = (float*)d_out;

    const int nb = out_size / 4;   // 4 batches per CTA
    tx_kernel<<<nb, 128, KV_TOTALF * sizeof(float)>>>(
        x, proj_w, proj_b, pos, in_proj_w, in_proj_b,
        out_w, out_b, ln1_g, ln1_b, lin1_w, lin1_b,
        lin2_w, lin2_b, ln2_g, ln2_b, head_w, head_b, out);
}

// round 17
// speedup vs baseline: 1.0587x; 1.0587x over previous
#include <cuda_runtime.h>
#include <cuda_bf16.h>

// Model dims
#define KTOK 64
#define DIN  49
#define DM   16
#define FFD  32

// XOR-swizzled KV layout: 16B chunk p (0..7) of row j stored at
//   j*32 + ((p ^ (j&7)) << 2) floats.
// Row = 32 floats (K[16] | V[16]) = 8 chunks. Writes: lane l writes row l
// (and l+32, same l&7): for fixed p the lanes cover all 8 bank groups ->
// 4-way conflict = the 4-wavefront minimum for STS.128. Reads are
// warp-uniform broadcasts (conflict-free); with j&7 a compile-time literal
// the permutation is free.
#define KV_BATCHF 2048                   // floats per batch
#define KV_TOTALF (4 * KV_BATCHF)        // 8192 floats = 32768 B dynamic smem
#define XCHUNK    1568                   // 32 rows * 49 floats per batch chunk

typedef unsigned long long u64;

__device__ __forceinline__ u64 splat2(float v) {
    u64 r; unsigned u = __float_as_uint(v);
    asm("mov.b64 %0, {%1, %1};" : "=l"(r) : "r"(u));
    return r;
}
__device__ __forceinline__ void ffma2(u64& d, u64 a, u64 b) {
    asm("fma.rn.f32x2 %0, %1, %2, %3;" : "=l"(d) : "l"(a), "l"(b), "l"(d));
}
__device__ __forceinline__ u64 mul2(u64 a, u64 b) {
    u64 r; asm("mul.rn.f32x2 %0, %1, %2;" : "=l"(r) : "l"(a), "l"(b)); return r;
}
__device__ __forceinline__ u64 add2(u64 a, u64 b) {
    u64 r; asm("add.rn.f32x2 %0, %1, %2;" : "=l"(r) : "l"(a), "l"(b)); return r;
}
__device__ __forceinline__ float2 unpack2(u64 p) {
    unsigned lo, hi;
    asm("mov.b64 {%0, %1}, %2;" : "=r"(lo), "=r"(hi) : "l"(p));
    return make_float2(__uint_as_float(lo), __uint_as_float(hi));
}

struct __align__(16) SW {            // 3044 floats = 12176 B (posw in global/L2)
    float pwt[DIN * DM];     // [i][d]
    float wqkvt[DM * 48];    // [d][e]
    float wot[DM * DM];      // [d][o]
    float w1t[DM * FFD];     // [d][f]
    float w2t[FFD * DM];     // [f][o]
    float pb[DM];
    float bqkv[48];
    float ob[DM];
    float ln1g[DM], ln1b[DM];
    float b1[FFD];
    float b2[DM];
    float ln2g[DM], ln2b[DM];
    float hw[DM];
    float hb;
    float pad[3];
};

__global__ void __launch_bounds__(128, 5)
tx_kernel(const float* __restrict__ x,
          const float* __restrict__ proj_w, const float* __restrict__ proj_b,
          const float* __restrict__ pos,
          const float* __restrict__ in_proj_w, const float* __restrict__ in_proj_b,
          const float* __restrict__ out_w, const float* __restrict__ out_b,
          const float* __restrict__ ln1_g, const float* __restrict__ ln1_b,
          const float* __restrict__ lin1_w, const float* __restrict__ lin1_b,
          const float* __restrict__ lin2_w, const float* __restrict__ lin2_b,
          const float* __restrict__ ln2_g, const float* __restrict__ ln2_b,
          const float* __restrict__ head_w, const float* __restrict__ head_b,
          float* __restrict__ out)
{
    __shared__ SW sw;
    extern __shared__ __align__(16) float kvbuf[];   // x staging, then K/V

    const int tid = threadIdx.x;

    for (int idx = tid; idx < DIN * DM; idx += 128) {
        int i = idx >> 4, d = idx & 15;
        sw.pwt[idx] = proj_w[d * DIN + i];
    }
    for (int idx = tid; idx < DM * 48; idx += 128) {
        int d = idx / 48, e = idx % 48;
        sw.wqkvt[idx] = in_proj_w[e * DM + d];
    }
    for (int idx = tid; idx < DM * DM; idx += 128) {
        int d = idx >> 4, o = idx & 15;
        sw.wot[idx] = out_w[o * DM + d];
    }
    for (int idx = tid; idx < DM * FFD; idx += 128) {
        int d = idx >> 5, f = idx & 31;
        sw.w1t[idx] = lin1_w[f * DM + d];
    }
    for (int idx = tid; idx < FFD * DM; idx += 128) {
        int f = idx >> 4, o = idx & 15;
        sw.w2t[idx] = lin2_w[o * FFD + f];
    }
    if (tid < DM) {
        sw.pb[tid]   = proj_b[tid];
        sw.ob[tid]   = out_b[tid];
        sw.ln1g[tid] = ln1_g[tid];
        sw.ln1b[tid] = ln1_b[tid];
        sw.b2[tid]   = lin2_b[tid];
        sw.ln2g[tid] = ln2_g[tid];
        sw.ln2b[tid] = ln2_b[tid];
        sw.hw[tid]   = head_w[tid];
    }
    if (tid < 48) sw.bqkv[tid] = in_proj_b[tid];
    if (tid < FFD) sw.b1[tid]  = lin1_b[tid];
    if (tid == 0)  sw.hb = head_b[0];

    const int b0   = blockIdx.x * 4;
    const int g    = tid >> 5;        // warp <-> batch
    const int lane = tid & 31;        // tokens: lane, lane+32

    // prefetch pos rows for both tokens from global (4KB table, L2-resident)
    u64 pos0[8], pos1[8];
    {
        const ulonglong2* pg0 = reinterpret_cast<const ulonglong2*>(pos + lane * DM);
        const ulonglong2* pg1 = reinterpret_cast<const ulonglong2*>(pos + (lane + 32) * DM);
#pragma unroll
        for (int p = 0; p < 4; p++) {
            ulonglong2 t0 = pg0[p], t1 = pg1[p];
            pos0[2*p] = t0.x; pos0[2*p+1] = t0.y;
            pos1[2*p] = t1.x; pos1[2*p+1] = t1.y;
        }
    }

    float h0[DM], h1[DM];

    // ---- stage 1: proj + bias + pos, chunked x staging ----
    const float4* xg = reinterpret_cast<const float4*>(x);
#pragma unroll
    for (int c = 0; c < 2; c++) {
        __syncthreads();
        float4* dst = reinterpret_cast<float4*>(kvbuf);
        for (int idx = tid; idx < 1568; idx += 128) {
            int gg  = idx / 392;
            int off = idx - gg * 392;
            dst[idx] = xg[(size_t)(b0 + gg) * 784 + c * 392 + off];
        }
        __syncthreads();

        u64 h2[8];
        const ulonglong2* pb2 = reinterpret_cast<const ulonglong2*>(sw.pb);
        const u64* pw = c ? pos1 : pos0;
#pragma unroll
        for (int p = 0; p < 4; p++) {
            ulonglong2 bq = pb2[p];
            h2[2*p]   = add2(bq.x, pw[2*p]);
            h2[2*p+1] = add2(bq.y, pw[2*p+1]);
        }
        const float* xrow = kvbuf + g * XCHUNK + lane * DIN;
#pragma unroll 7
        for (int i = 0; i < DIN; i++) {
            u64 xv = splat2(xrow[i]);
            const ulonglong2* wr = reinterpret_cast<const ulonglong2*>(&sw.pwt[i * DM]);
            ulonglong2 w0 = wr[0], w1 = wr[1], w2 = wr[2], w3 = wr[3];
            ffma2(h2[0], xv, w0.x); ffma2(h2[1], xv, w0.y);
            ffma2(h2[2], xv, w1.x); ffma2(h2[3], xv, w1.y);
            ffma2(h2[4], xv, w2.x); ffma2(h2[5], xv, w2.y);
            ffma2(h2[6], xv, w3.x); ffma2(h2[7], xv, w3.y);
        }
        float* hh = c ? h1 : h0;
#pragma unroll
        for (int p = 0; p < 8; p++) {
            float2 t = unpack2(h2[p]); hh[2*p] = t.x; hh[2*p+1] = t.y;
        }
    }
    __syncthreads();   // x reads done; kvbuf becomes K/V

    // ---- stage 2a: K,V projection for both tokens, swizzled smem write ----
    {
        u64 kv0[16], kv1[16];
        const ulonglong2* bq = reinterpret_cast<const ulonglong2*>(sw.bqkv + 16);
#pragma unroll
        for (int p = 0; p < 8; p++) {
            ulonglong2 t = bq[p];
            kv0[2*p] = t.x; kv0[2*p+1] = t.y;
            kv1[2*p] = t.x; kv1[2*p+1] = t.y;
        }
#pragma unroll
        for (int d = 0; d < DM; d++) {
            u64 hv0 = splat2(h0[d]), hv1 = splat2(h1[d]);
            const ulonglong2* wr = reinterpret_cast<const ulonglong2*>(&sw.wqkvt[d * 48 + 16]);
#pragma unroll
            for (int p = 0; p < 8; p++) {
                ulonglong2 w = wr[p];
                ffma2(kv0[2*p],   hv0, w.x); ffma2(kv0[2*p+1], hv0, w.y);
                ffma2(kv1[2*p],   hv1, w.x); ffma2(kv1[2*p+1], hv1, w.y);
            }
        }
        const int u = lane & 7;   // (lane+32)&7 == lane&7
        ulonglong2* r0 = reinterpret_cast<ulonglong2*>(kvbuf + g * KV_BATCHF + lane * 32);
        ulonglong2* r1 = r0 + 256;   // row lane+32 = +1024 floats
#pragma unroll
        for (int p = 0; p < 8; p++) {
            r0[p ^ u] = make_ulonglong2(kv0[2*p], kv0[2*p+1]);
            r1[p ^ u] = make_ulonglong2(kv1[2*p], kv1[2*p+1]);
        }
    }

    // ---- stage 2b: Q projection (pre-scaled by 1/sqrt(8)) ----
    u64 q0[8], q1[8];
    {
        const ulonglong2* bq = reinterpret_cast<const ulonglong2*>(sw.bqkv);
#pragma unroll
        for (int p = 0; p < 4; p++) {
            ulonglong2 t = bq[p];
            q0[2*p] = t.x; q0[2*p+1] = t.y;
            q1[2*p] = t.x; q1[2*p+1] = t.y;
        }
#pragma unroll
        for (int d = 0; d < DM; d++) {
            u64 hv0 = splat2(h0[d]), hv1 = splat2(h1[d]);
            const ulonglong2* wr = reinterpret_cast<const ulonglong2*>(&sw.wqkvt[d * 48]);
#pragma unroll
            for (int p = 0; p < 4; p++) {
                ulonglong2 w = wr[p];
                ffma2(q0[2*p],   hv0, w.x); ffma2(q0[2*p+1], hv0, w.y);
                ffma2(q1[2*p],   hv1, w.x); ffma2(q1[2*p+1], hv1, w.y);
            }
        }
        u64 sc2 = splat2(0.35355339059327373f);
#pragma unroll
        for (int p = 0; p < 8; p++) { q0[p] = mul2(q0[p], sc2); q1[p] = mul2(q1[p], sc2); }
    }
    __syncwarp();   // KV rows are warp-private (warp <-> batch)

    // ---- stage 3: attention, single pass, no max subtraction ----
    // |scores| << 1 by input construction; exp() safe, math identical to
    // max-subtracted softmax. Nested 8x8 loop: inner fully unrolled so the
    // XOR chunk permutation (j&7) is compile-time.
    float ctx0[DM], ctx1[DM];
    {
        const float* kvb = kvbuf + g * KV_BATCHF;
        float s00 = 0.f, s01 = 0.f, s10 = 0.f, s11 = 0.f;
        u64 ca0[8], ca1[8];
#pragma unroll
        for (int p = 0; p < 8; p++) { ca0[p] = 0ull; ca1[p] = 0ull; }
        for (int jb = 0; jb < KTOK; jb += 8) {
            const ulonglong2* krb = reinterpret_cast<const ulonglong2*>(kvb + jb * 32);
#pragma unroll
            for (int uj = 0; uj < 8; uj++) {
                const ulonglong2* kr = krb + uj * 8;
                // logical chunk p at physical index p ^ uj (literal)
                ulonglong2 k0 = kr[0 ^ uj], k1 = kr[1 ^ uj];
                ulonglong2 k2 = kr[2 ^ uj], k3 = kr[3 ^ uj];
                u64 a00 = mul2(q0[0], k0.x);
                ffma2(a00, q0[1], k0.y); ffma2(a00, q0[2], k1.x); ffma2(a00, q0[3], k1.y);
                u64 a01 = mul2(q0[4], k2.x);
                ffma2(a01, q0[5], k2.y); ffma2(a01, q0[6], k3.x); ffma2(a01, q0[7], k3.y);
                u64 a10 = mul2(q1[0], k0.x);
                ffma2(a10, q1[1], k0.y); ffma2(a10, q1[2], k1.x); ffma2(a10, q1[3], k1.y);
                u64 a11 = mul2(q1[4], k2.x);
                ffma2(a11, q1[5], k2.y); ffma2(a11, q1[6], k3.x); ffma2(a11, q1[7], k3.y);

                float2 t00 = unpack2(a00), t01 = unpack2(a01);
                float2 t10 = unpack2(a10), t11 = unpack2(a11);
                float e00 = __expf(t00.x + t00.y);
                float e01 = __expf(t01.x + t01.y);
                float e10 = __expf(t10.x + t10.y);
                float e11 = __expf(t11.x + t11.y);
                s00 += e00; s01 += e01; s10 += e10; s11 += e11;

                ulonglong2 v0 = kr[4 ^ uj], v1 = kr[5 ^ uj];
                ulonglong2 v2 = kr[6 ^ uj], v3 = kr[7 ^ uj];
                u64 p00 = splat2(e00), p01 = splat2(e01);
                u64 p10 = splat2(e10), p11 = splat2(e11);
                ffma2(ca0[0], p00, v0.x); ffma2(ca0[1], p00, v0.y);
                ffma2(ca0[2], p00, v1.x); ffma2(ca0[3], p00, v1.y);
                ffma2(ca0[4], p01, v2.x); ffma2(ca0[5], p01, v2.y);
                ffma2(ca0[6], p01, v3.x); ffma2(ca0[7], p01, v3.y);
                ffma2(ca1[0], p10, v0.x); ffma2(ca1[1], p10, v0.y);
                ffma2(ca1[2], p10, v1.x); ffma2(ca1[3], p10, v1.y);
                ffma2(ca1[4], p11, v2.x); ffma2(ca1[5], p11, v2.y);
                ffma2(ca1[6], p11, v3.x); ffma2(ca1[7], p11, v3.y);
            }
        }
        float i00 = __fdividef(1.0f, s00), i01 = __fdividef(1.0f, s01);
        float i10 = __fdividef(1.0f, s10), i11 = __fdividef(1.0f, s11);
#pragma unroll
        for (int p = 0; p < 8; p++) {
            float2 t0 = unpack2(ca0[p]), t1 = unpack2(ca1[p]);
            float f0 = (p < 4) ? i00 : i01;
            float f1 = (p < 4) ? i10 : i11;
            ctx0[2*p] = t0.x * f0; ctx0[2*p+1] = t0.y * f0;
            ctx1[2*p] = t1.x * f1; ctx1[2*p+1] = t1.y * f1;
        }
    }

    // ---- stage 4: out proj + residual + LN1 ----
    {
        u64 ao0[8], ao1[8];
        const ulonglong2* ob2 = reinterpret_cast<const ulonglong2*>(sw.ob);
#pragma unroll
        for (int p = 0; p < 4; p++) {
            ulonglong2 t = ob2[p];
            ao0[2*p] = t.x; ao0[2*p+1] = t.y;
            ao1[2*p] = t.x; ao1[2*p+1] = t.y;
        }
#pragma unroll
        for (int d = 0; d < DM; d++) {
            u64 c0 = splat2(ctx0[d]), c1 = splat2(ctx1[d]);
            const ulonglong2* wr = reinterpret_cast<const ulonglong2*>(&sw.wot[d * DM]);
#pragma unroll
            for (int p = 0; p < 4; p++) {
                ulonglong2 w = wr[p];
                ffma2(ao0[2*p],   c0, w.x); ffma2(ao0[2*p+1], c0, w.y);
                ffma2(ao1[2*p],   c1, w.x); ffma2(ao1[2*p+1], c1, w.y);
            }
        }
#pragma unroll
        for (int p = 0; p < 8; p++) {
            float2 t0 = unpack2(ao0[p]), t1 = unpack2(ao1[p]);
            h0[2*p] += t0.x; h0[2*p+1] += t0.y;
            h1[2*p] += t1.x; h1[2*p+1] += t1.y;
        }
#pragma unroll
        for (int t = 0; t < 2; t++) {
            float* hh = t ? h1 : h0;
            float mu = 0.f;
#pragma unroll
            for (int d = 0; d < DM; d++) mu += hh[d];
            mu *= (1.0f / 16.0f);
            float var = 0.f;
#pragma unroll
            for (int d = 0; d < DM; d++) { float z = hh[d] - mu; var = fmaf(z, z, var); }
            var *= (1.0f / 16.0f);
            float rstd = rsqrtf(var + 1e-5f);
#pragma unroll
            for (int d = 0; d < DM; d++)
                hh[d] = (hh[d] - mu) * rstd * sw.ln1g[d] + sw.ln1b[d];
        }
    }

    // ---- stage 5: FFN + residual + LN2 ----
    {
        u64 ff0[16], ff1[16];
        const ulonglong2* b12 = reinterpret_cast<const ulonglong2*>(sw.b1);
#pragma unroll
        for (int p = 0; p < 8; p++) {
            ulonglong2 t = b12[p];
            ff0[2*p] = t.x; ff0[2*p+1] = t.y;
            ff1[2*p] = t.x; ff1[2*p+1] = t.y;
        }
#pragma unroll
        for (int d = 0; d < DM; d++) {
            u64 hv0 = splat2(h0[d]), hv1 = splat2(h1[d]);
            const ulonglong2* wr = reinterpret_cast<const ulonglong2*>(&sw.w1t[d * FFD]);
#pragma unroll
            for (int p = 0; p < 8; p++) {
                ulonglong2 w = wr[p];
                ffma2(ff0[2*p],   hv0, w.x); ffma2(ff0[2*p+1], hv0, w.y);
                ffma2(ff1[2*p],   hv1, w.x); ffma2(ff1[2*p+1], hv1, w.y);
            }
        }
        u64 f20[8], f21[8];
        const ulonglong2* b22 = reinterpret_cast<const ulonglong2*>(sw.b2);
#pragma unroll
        for (int p = 0; p < 4; p++) {
            ulonglong2 t = b22[p];
            f20[2*p] = t.x; f20[2*p+1] = t.y;
            f21[2*p] = t.x; f21[2*p+1] = t.y;
        }
#pragma unroll
        for (int p = 0; p < 16; p++) {           // f = 2p (x), 2p+1 (y)
            float2 u0 = unpack2(ff0[p]), u1 = unpack2(ff1[p]);
            float fa0 = fmaxf(u0.x, 0.f), fb0 = fmaxf(u0.y, 0.f);
            float fa1 = fmaxf(u1.x, 0.f), fb1 = fmaxf(u1.y, 0.f);
            u64 sa0 = splat2(fa0), sb0 = splat2(fb0);
            u64 sa1 = splat2(fa1), sb1 = splat2(fb1);
            const ulonglong2* wa = reinterpret_cast<const ulonglong2*>(&sw.w2t[(2*p) * DM]);
            const ulonglong2* wb = reinterpret_cast<const ulonglong2*>(&sw.w2t[(2*p+1) * DM]);
            ulonglong2 wa0 = wa[0], wa1 = wa[1], wa2 = wa[2], wa3 = wa[3];
            ffma2(f20[0], sa0, wa0.x); ffma2(f20[1], sa0, wa0.y);
            ffma2(f20[2], sa0, wa1.x); ffma2(f20[3], sa0, wa1.y);
            ffma2(f20[4], sa0, wa2.x); ffma2(f20[5], sa0, wa2.y);
            ffma2(f20[6], sa0, wa3.x); ffma2(f20[7], sa0, wa3.y);
            ffma2(f21[0], sa1, wa0.x); ffma2(f21[1], sa1, wa0.y);
            ffma2(f21[2], sa1, wa1.x); ffma2(f21[3], sa1, wa1.y);
            ffma2(f21[4], sa1, wa2.x); ffma2(f21[5], sa1, wa2.y);
            ffma2(f21[6], sa1, wa3.x); ffma2(f21[7], sa1, wa3.y);
            ulonglong2 wb0 = wb[0], wb1 = wb[1], wb2 = wb[2], wb3 = wb[3];
            ffma2(f20[0], sb0, wb0.x); ffma2(f20[1], sb0, wb0.y);
            ffma2(f20[2], sb0, wb1.x); ffma2(f20[3], sb0, wb1.y);
            ffma2(f20[4], sb0, wb2.x); ffma2(f20[5], sb0, wb2.y);
            ffma2(f20[6], sb0, wb3.x); ffma2(f20[7], sb0, wb3.y);
            ffma2(f21[0], sb1, wb0.x); ffma2(f21[1], sb1, wb0.y);
            ffma2(f21[2], sb1, wb1.x); ffma2(f21[3], sb1, wb1.y);
            ffma2(f21[4], sb1, wb2.x); ffma2(f21[5], sb1, wb2.y);
            ffma2(f21[6], sb1, wb3.x); ffma2(f21[7], sb1, wb3.y);
        }
#pragma unroll
        for (int p = 0; p < 8; p++) {
            float2 t0 = unpack2(f20[p]), t1 = unpack2(f21[p]);
            h0[2*p] += t0.x; h0[2*p+1] += t0.y;
            h1[2*p] += t1.x; h1[2*p+1] += t1.y;
        }
#pragma unroll
        for (int t = 0; t < 2; t++) {
            float* hh = t ? h1 : h0;
            float mu = 0.f;
#pragma unroll
            for (int d = 0; d < DM; d++) mu += hh[d];
            mu *= (1.0f / 16.0f);
            float var = 0.f;
#pragma unroll
            for (int d = 0; d < DM; d++) { float z = hh[d] - mu; var = fmaf(z, z, var); }
            var *= (1.0f / 16.0f);
            float rstd = rsqrtf(var + 1e-5f);
#pragma unroll
            for (int d = 0; d < DM; d++)
                hh[d] = (hh[d] - mu) * rstd * sw.ln2g[d] + sw.ln2b[d];
        }
    }

    // ---- stage 6: head dot + mean pool (warp == batch) ----
    float sc = 0.f;
#pragma unroll
    for (int d = 0; d < DM; d++) sc = fmaf(h0[d], sw.hw[d], sc);
#pragma unroll
    for (int d = 0; d < DM; d++) sc = fmaf(h1[d], sw.hw[d], sc);
#pragma unroll
    for (int off = 16; off >= 1; off >>= 1)
        sc += __shfl_xor_sync(0xffffffffu, sc, off);
    if (lane == 0)
        out[b0 + g] = sc * (1.0f / 64.0f) + sw.hb;
}

extern "C" void kernel_launch(void* const* d_in, const int* in_sizes, int n_in,
                              void* d_out, int out_size)
{
    const float* x         = (const float*)d_in[0];
    const float* proj_w    = (const float*)d_in[1];
    const float* proj_b    = (const float*)d_in[2];
    const float* pos       = (const float*)d_in[3];
    const float* in_proj_w = (const float*)d_in[4];
    const float* in_proj_b = (const float*)d_in[5];
    const float* out_w     = (const float*)d_in[6];
    const float* out_b     = (const float*)d_in[7];
    const float* ln1_g     = (const float*)d_in[8];
    const float* ln1_b     = (const float*)d_in[9];
    const float* lin1_w    = (const float*)d_in[10];
    const float* lin1_b    = (const float*)d_in[11];
    const float* lin2_w    = (const float*)d_in[12];
    const float* lin2_b    = (const float*)d_in[13];
    const float* ln2_g     = (const float*)d_in[14];
    const float* ln2_b     = (const float*)d_in[15];
    const float* head_w    = (const float*)d_in[16];
    const float* head_b    = (const float*)d_in[17];
    float* out = (float*)d_out;

    const int nb = out_size / 4;   // 4 batches per CTA
    tx_kernel<<<nb, 128, KV_TOTALF * sizeof(float)>>>(
        x, proj_w, proj_b, pos, in_proj_w, in_proj_b,
        out_w, out_b, ln1_g, ln1_b, lin1_w, lin1_b,
        lin2_w, lin2_b, ln2_g, ln2_b, head_w, head_b, out);
}